// round 4
// baseline (speedup 1.0000x reference)
#include <cuda_runtime.h>
#include <cuda_bf16.h>
#include <math.h>

#define HW 16384           // 128*128
#define KC 192

// Scratch (static device globals: allocation-free per harness rules)
__device__ float g_qkv[(size_t)8 * 576 * HW];   // [B][576][H][W]  (qk first 384, v last 192)
__device__ float g_y  [(size_t)8 * 192 * HW];   // [B][192][H][W]
__device__ float g_bias[6 * 64 * 64];           // [NH][N][N]

// ---------------------------------------------------------------------------
// Relative-position bias via meta MLP (input-independent per launch)
// ---------------------------------------------------------------------------
__global__ void bias_kernel(const float* __restrict__ w1, const float* __restrict__ b1,
                            const float* __restrict__ w2, const float* __restrict__ b2)
{
    int idx = blockIdx.x * 256 + threadIdx.x;   // 0..4095
    int n = idx >> 6, m = idx & 63;
    float d0 = (float)((n >> 3) - (m >> 3));
    float d1 = (float)((n & 7) - (m & 7));
    float r0 = copysignf(log1pf(fabsf(d0)), d0);
    float r1 = copysignf(log1pf(fabsf(d1)), d1);
    float acc[6];
#pragma unroll
    for (int h = 0; h < 6; h++) acc[h] = b2[h];
    for (int t = 0; t < 256; t++) {
        float hval = fmaxf(r0 * w1[t] + r1 * w1[256 + t] + b1[t], 0.0f);
#pragma unroll
        for (int h = 0; h < 6; h++) acc[h] += hval * w2[t * 6 + h];
    }
#pragma unroll
    for (int h = 0; h < 6; h++) g_bias[h * 4096 + n * 64 + m] = acc[h];
}

// ---------------------------------------------------------------------------
// 1x1 conv as GEMM: out[b][m0+m][p] = sum_k W[m][k] * x[b][k][p] + bias[m]
// Tile 64(M) x 128(P), BK=32, 256 threads, 4x8 per thread.
// Register-staged software pipeline over K-steps.
// ---------------------------------------------------------------------------
__global__ __launch_bounds__(256) void gemm1x1(
    const float* __restrict__ W, const float* __restrict__ bias,
    const float* __restrict__ x, float* __restrict__ out,
    size_t outBatchStride)
{
    __shared__ float As[32 * 65];    // As[k][m], pitch 65
    __shared__ float Bs[32 * 128];   // Bs[k][p]
    const float* xb = x + (size_t)blockIdx.z * KC * HW;
    float* ob = out + (size_t)blockIdx.z * outBatchStride;
    int m0 = blockIdx.y * 64, p0 = blockIdx.x * 128;
    int tid = threadIdx.x;
    int tm = (tid >> 4) * 4, tn = (tid & 15) * 8;

    // per-thread load coordinates (fixed across K-steps)
    int am = tid >> 5, ak = tid & 31;              // A: 8 rows per thread, stride 8 in m
    int bk = tid >> 5, bp4 = tid & 31;             // B: 4 k-rows per thread, stride 8 in k

    float acc[4][8] = {};
    float aReg[8];
    float4 bReg[4];

    // prologue: load k0 = 0
#pragma unroll
    for (int i = 0; i < 8; i++)
        aReg[i] = W[(size_t)(m0 + am + i * 8) * KC + ak];
#pragma unroll
    for (int i = 0; i < 4; i++)
        bReg[i] = *(const float4*)&xb[(size_t)(bk + i * 8) * HW + p0 + bp4 * 4];

    for (int k0 = 0; k0 < KC; k0 += 32) {
        // commit staged tile to smem
#pragma unroll
        for (int i = 0; i < 8; i++)
            As[ak * 65 + am + i * 8] = aReg[i];
#pragma unroll
        for (int i = 0; i < 4; i++)
            *(float4*)&Bs[(bk + i * 8) * 128 + bp4 * 4] = bReg[i];
        __syncthreads();

        // prefetch next tile into registers (overlaps with compute below)
        if (k0 + 32 < KC) {
#pragma unroll
            for (int i = 0; i < 8; i++)
                aReg[i] = W[(size_t)(m0 + am + i * 8) * KC + k0 + 32 + ak];
#pragma unroll
            for (int i = 0; i < 4; i++)
                bReg[i] = *(const float4*)&xb[(size_t)(k0 + 32 + bk + i * 8) * HW + p0 + bp4 * 4];
        }

#pragma unroll
        for (int k = 0; k < 32; k++) {
            float a0 = As[k * 65 + tm];
            float a1 = As[k * 65 + tm + 1];
            float a2 = As[k * 65 + tm + 2];
            float a3 = As[k * 65 + tm + 3];
            float4 b0 = *(const float4*)&Bs[k * 128 + tn];
            float4 b1 = *(const float4*)&Bs[k * 128 + tn + 4];
            acc[0][0] += a0 * b0.x; acc[0][1] += a0 * b0.y; acc[0][2] += a0 * b0.z; acc[0][3] += a0 * b0.w;
            acc[0][4] += a0 * b1.x; acc[0][5] += a0 * b1.y; acc[0][6] += a0 * b1.z; acc[0][7] += a0 * b1.w;
            acc[1][0] += a1 * b0.x; acc[1][1] += a1 * b0.y; acc[1][2] += a1 * b0.z; acc[1][3] += a1 * b0.w;
            acc[1][4] += a1 * b1.x; acc[1][5] += a1 * b1.y; acc[1][6] += a1 * b1.z; acc[1][7] += a1 * b1.w;
            acc[2][0] += a2 * b0.x; acc[2][1] += a2 * b0.y; acc[2][2] += a2 * b0.z; acc[2][3] += a2 * b0.w;
            acc[2][4] += a2 * b1.x; acc[2][5] += a2 * b1.y; acc[2][6] += a2 * b1.z; acc[2][7] += a2 * b1.w;
            acc[3][0] += a3 * b0.x; acc[3][1] += a3 * b0.y; acc[3][2] += a3 * b0.z; acc[3][3] += a3 * b0.w;
            acc[3][4] += a3 * b1.x; acc[3][5] += a3 * b1.y; acc[3][6] += a3 * b1.z; acc[3][7] += a3 * b1.w;
        }
        __syncthreads();
    }
#pragma unroll
    for (int i = 0; i < 4; i++) {
        float bv = bias[m0 + tm + i];
        float4 r0 = make_float4(acc[i][0] + bv, acc[i][1] + bv, acc[i][2] + bv, acc[i][3] + bv);
        float4 r1 = make_float4(acc[i][4] + bv, acc[i][5] + bv, acc[i][6] + bv, acc[i][7] + bv);
        float* orow = &ob[(size_t)(m0 + tm + i) * HW + p0 + tn];
        *(float4*)orow = r0;
        *(float4*)(orow + 4) = r1;
    }
}

// ---------------------------------------------------------------------------
// Fused per-(window, head) attention:
//   o = circular_conv_8x8(q*scale, k)  (per channel d)
//   attn = softmax(o @ v^T + bias[head])
//   y = attn @ v  -> scattered back to [B,192,H,W]
// grid: (2048 windows, 6 heads), 256 threads
// ---------------------------------------------------------------------------
__global__ __launch_bounds__(256) void attn_kernel()
{
    __shared__ float smem[8832];
    float* q_s    = smem;          // [64][33]
    float* k_s    = smem + 2112;   // [64][33]
    float* attn_s = smem;          // [64][66], overlays q/k after o-stage
    float* v_s    = smem + 4224;   // [64][36]
    float* o_s    = smem + 6528;   // [64][36]

    int win = blockIdx.x, head = blockIdx.y;
    int b = win >> 8, wi = win & 255;
    int h0 = (wi >> 4) * 8, w0 = (wi & 15) * 8;
    int tid = threadIdx.x;
    const float* qkv_b = g_qkv + (size_t)b * 576 * HW;
    const float SCALE = 0.17677669529663687f;   // 32^-0.5

    // ---- load q,k,v tiles ----
#pragma unroll
    for (int i = 0; i < 8; i++) {
        int idx = tid + i * 256;
        int d = idx >> 6, n = idx & 63;
        int pos = (h0 + (n >> 3)) * 128 + w0 + (n & 7);
        int cq = head * 32 + d;
        q_s[n * 33 + d] = qkv_b[(size_t)cq * HW + pos] * SCALE;
        k_s[n * 33 + d] = qkv_b[(size_t)(192 + cq) * HW + pos];
        v_s[n * 36 + d] = qkv_b[(size_t)(384 + cq) * HW + pos];
    }
    __syncthreads();

    // ---- o stage: 8x8 circular convolution per channel ----
    // thread: d = lane, warp -> row ni; computes o[ni*8 + r][d], r=0..7
    {
        int d = tid & 31, warp = tid >> 5;
        float acc[8] = {0, 0, 0, 0, 0, 0, 0, 0};
#pragma unroll
        for (int mi = 0; mi < 8; mi++) {
            int crow = (warp - mi) & 7;
            float krow[8];
#pragma unroll
            for (int j = 0; j < 8; j++) krow[j] = k_s[(crow * 8 + j) * 33 + d];
#pragma unroll
            for (int mj = 0; mj < 8; mj++) {
                float qv = q_s[(mi * 8 + mj) * 33 + d];
#pragma unroll
                for (int r = 0; r < 8; r++) acc[r] += qv * krow[(r - mj) & 7];
            }
        }
#pragma unroll
        for (int r = 0; r < 8; r++) o_s[(warp * 8 + r) * 36 + d] = acc[r];
    }
    __syncthreads();

    // ---- attn logits: attn[n][m] = bias + sum_d o[n][d]*v[m][d] ----
    {
        int n = tid & 63, mblk = tid >> 6;   // 16 m per thread
        const float* bh = g_bias + head * 4096 + n * 64 + mblk * 16;
        float acc[16];
#pragma unroll
        for (int j = 0; j < 16; j++) acc[j] = bh[j];
#pragma unroll
        for (int d4 = 0; d4 < 8; d4++) {
            float4 ov = *(const float4*)&o_s[n * 36 + d4 * 4];
#pragma unroll
            for (int j = 0; j < 16; j++) {
                float4 vv = *(const float4*)&v_s[(mblk * 16 + j) * 36 + d4 * 4];
                acc[j] += ov.x * vv.x + ov.y * vv.y + ov.z * vv.z + ov.w * vv.w;
            }
        }
        // q/k region dead since last sync -> safe to overlay attn_s
#pragma unroll
        for (int j = 0; j < 16; j++) attn_s[n * 66 + mblk * 16 + j] = acc[j];
    }
    __syncthreads();

    // ---- softmax over m (one thread per row) ----
    if (tid < 64) {
        float mx = -1e30f;
        for (int m = 0; m < 64; m++) mx = fmaxf(mx, attn_s[tid * 66 + m]);
        float s = 0.0f;
        for (int m = 0; m < 64; m++) {
            float e = __expf(attn_s[tid * 66 + m] - mx);
            attn_s[tid * 66 + m] = e;
            s += e;
        }
        float inv = 1.0f / s;
        for (int m = 0; m < 64; m++) attn_s[tid * 66 + m] *= inv;
    }
    __syncthreads();

    // ---- y = attn @ v, scatter to g_y ----
    {
        int n = tid >> 2, dblk = (tid & 3) * 8;
        float acc[8] = {0, 0, 0, 0, 0, 0, 0, 0};
#pragma unroll 16
        for (int m = 0; m < 64; m++) {
            float a = attn_s[n * 66 + m];
            float4 v0 = *(const float4*)&v_s[m * 36 + dblk];
            float4 v1 = *(const float4*)&v_s[m * 36 + dblk + 4];
            acc[0] += a * v0.x; acc[1] += a * v0.y; acc[2] += a * v0.z; acc[3] += a * v0.w;
            acc[4] += a * v1.x; acc[5] += a * v1.y; acc[6] += a * v1.z; acc[7] += a * v1.w;
        }
        int pos = (h0 + (n >> 3)) * 128 + w0 + (n & 7);
        float* yb = g_y + (size_t)b * 192 * HW + pos;
#pragma unroll
        for (int i = 0; i < 8; i++)
            yb[(size_t)(head * 32 + dblk + i) * HW] = acc[i];
    }
}

// ---------------------------------------------------------------------------
extern "C" void kernel_launch(void* const* d_in, const int* in_sizes, int n_in,
                              void* d_out, int out_size)
{
    const float* x      = (const float*)d_in[0];
    const float* V_w    = (const float*)d_in[1];
    const float* V_b    = (const float*)d_in[2];
    const float* QK_w   = (const float*)d_in[3];
    const float* QK_b   = (const float*)d_in[4];
    const float* proj_w = (const float*)d_in[5];
    const float* proj_b = (const float*)d_in[6];
    const float* mw1    = (const float*)d_in[7];
    const float* mb1    = (const float*)d_in[8];
    const float* mw2    = (const float*)d_in[9];
    const float* mb2    = (const float*)d_in[10];
    float* out = (float*)d_out;

    void* p;
    cudaGetSymbolAddress(&p, g_qkv); float* qkv = (float*)p;
    cudaGetSymbolAddress(&p, g_y);   float* y   = (float*)p;

    // 1) relative-position bias (meta MLP)
    bias_kernel<<<16, 256>>>(mw1, mb1, mw2, mb2);

    // 2) QK conv -> qkv[0:384), V conv -> qkv[384:576)
    gemm1x1<<<dim3(128, 6, 8), 256>>>(QK_w, QK_b, x, qkv,                    (size_t)576 * HW);
    gemm1x1<<<dim3(128, 3, 8), 256>>>(V_w,  V_b,  x, qkv + (size_t)384 * HW, (size_t)576 * HW);

    // 3) fused windowed attention (circular conv + bias + softmax + AV)
    attn_kernel<<<dim3(2048, 6), 256>>>();

    // 4) output projection
    gemm1x1<<<dim3(128, 3, 8), 256>>>(proj_w, proj_b, y, out, (size_t)192 * HW);
}

// round 11
// speedup vs baseline: 1.4816x; 1.4816x over previous
#include <cuda_runtime.h>
#include <cuda_bf16.h>
#include <math.h>

#define HW 16384           // 128*128
#define KC 192

// Scratch (static device globals: allocation-free per harness rules)
__device__ float g_qkv[(size_t)8 * 576 * HW];   // [B][576][H][W]  (qk first 384, v last 192)
__device__ float g_y  [(size_t)8 * 192 * HW];   // [B][192][H][W]
__device__ float g_bias[6 * 64 * 64];           // [NH][N][N]

// ---------------------------------------------------------------------------
// Relative-position bias via meta MLP (input-independent per launch)
// ---------------------------------------------------------------------------
__global__ void bias_kernel(const float* __restrict__ w1, const float* __restrict__ b1,
                            const float* __restrict__ w2, const float* __restrict__ b2)
{
    int idx = blockIdx.x * 256 + threadIdx.x;   // 0..4095
    int n = idx >> 6, m = idx & 63;
    float d0 = (float)((n >> 3) - (m >> 3));
    float d1 = (float)((n & 7) - (m & 7));
    float r0 = copysignf(log1pf(fabsf(d0)), d0);
    float r1 = copysignf(log1pf(fabsf(d1)), d1);
    float acc[6];
#pragma unroll
    for (int h = 0; h < 6; h++) acc[h] = b2[h];
    for (int t = 0; t < 256; t++) {
        float hval = fmaxf(r0 * w1[t] + r1 * w1[256 + t] + b1[t], 0.0f);
#pragma unroll
        for (int h = 0; h < 6; h++) acc[h] += hval * w2[t * 6 + h];
    }
#pragma unroll
    for (int h = 0; h < 6; h++) g_bias[h * 4096 + n * 64 + m] = acc[h];
}

// ---------------------------------------------------------------------------
// 1x1 conv as GEMM, 128M x 128P tile, BK=16, 256 threads, 8x8 per thread
// (split 4+4 register tiles). Rows [0,split) use W0/b0, [split,M) use W1/b1.
// Register-staged software pipeline over K-steps.
// ---------------------------------------------------------------------------
__global__ __launch_bounds__(256) void gemm128(
    const float* __restrict__ W0, const float* __restrict__ b0,
    const float* __restrict__ W1, const float* __restrict__ b1,
    int split, int M,
    const float* __restrict__ x, float* __restrict__ out, size_t outStride)
{
    __shared__ float As[16][132];   // As[k][m]
    __shared__ float Bs[16][132];   // Bs[k][p]
    const float* xb = x + (size_t)blockIdx.z * KC * HW;
    float* ob = out + (size_t)blockIdx.z * outStride;
    int m0 = blockIdx.y * 128, p0 = blockIdx.x * 128;
    int tid = threadIdx.x;

    // A load: row ar (2 threads/row), 8 consecutive k each (2 float4)
    int ar = tid >> 1, ac = (tid & 1) * 8;
    int grow = m0 + ar;
    const float* wp;
    if (grow < split)      wp = W0 + (size_t)grow * KC;
    else if (grow < M)     wp = W1 + (size_t)(grow - split) * KC;
    else                   wp = W0;             // dummy, loads zeroed
    bool avalid = grow < M;

    // B load: k-row bk (16 threads/row), two float4 at bp and bp+64
    int bk = tid >> 4, bp = (tid & 15) * 4;

    // compute fragment coords (4+4 split)
    int tmf = (tid >> 4) * 4;
    int tnf = (tid & 15) * 4;

    float acc[8][8] = {};
    float4 aR0, aR1, bR0, bR1;

    // prologue: k0 = 0
    if (avalid) { aR0 = *(const float4*)(wp + ac); aR1 = *(const float4*)(wp + ac + 4); }
    else        { aR0 = make_float4(0,0,0,0); aR1 = aR0; }
    bR0 = *(const float4*)&xb[(size_t)bk * HW + p0 + bp];
    bR1 = *(const float4*)&xb[(size_t)bk * HW + p0 + bp + 64];

    for (int k0 = 0; k0 < KC; k0 += 16) {
        // commit staged tiles
        As[ac + 0][ar] = aR0.x; As[ac + 1][ar] = aR0.y;
        As[ac + 2][ar] = aR0.z; As[ac + 3][ar] = aR0.w;
        As[ac + 4][ar] = aR1.x; As[ac + 5][ar] = aR1.y;
        As[ac + 6][ar] = aR1.z; As[ac + 7][ar] = aR1.w;
        *(float4*)&Bs[bk][bp]      = bR0;
        *(float4*)&Bs[bk][bp + 64] = bR1;
        __syncthreads();

        // prefetch next K-step (overlaps with compute)
        if (k0 + 16 < KC) {
            if (avalid) {
                aR0 = *(const float4*)(wp + k0 + 16 + ac);
                aR1 = *(const float4*)(wp + k0 + 16 + ac + 4);
            }
            bR0 = *(const float4*)&xb[(size_t)(k0 + 16 + bk) * HW + p0 + bp];
            bR1 = *(const float4*)&xb[(size_t)(k0 + 16 + bk) * HW + p0 + bp + 64];
        }

#pragma unroll
        for (int k = 0; k < 16; k++) {
            float4 a0 = *(const float4*)&As[k][tmf];
            float4 a1 = *(const float4*)&As[k][tmf + 64];
            float4 bb0 = *(const float4*)&Bs[k][tnf];
            float4 bb1 = *(const float4*)&Bs[k][tnf + 64];
            float am[8] = {a0.x, a0.y, a0.z, a0.w, a1.x, a1.y, a1.z, a1.w};
            float bn[8] = {bb0.x, bb0.y, bb0.z, bb0.w, bb1.x, bb1.y, bb1.z, bb1.w};
#pragma unroll
            for (int i = 0; i < 8; i++)
#pragma unroll
                for (int j = 0; j < 8; j++)
                    acc[i][j] += am[i] * bn[j];
        }
        __syncthreads();
    }

    // epilogue
#pragma unroll
    for (int i = 0; i < 8; i++) {
        int m = m0 + tmf + (i < 4 ? i : 60 + i);    // tmf+i or tmf+64+(i-4)
        if (m >= M) continue;
        float bv = (m < split) ? b0[m] : b1[m - split];
        float* orow = &ob[(size_t)m * HW + p0];
        float4 r0 = make_float4(acc[i][0] + bv, acc[i][1] + bv, acc[i][2] + bv, acc[i][3] + bv);
        float4 r1 = make_float4(acc[i][4] + bv, acc[i][5] + bv, acc[i][6] + bv, acc[i][7] + bv);
        *(float4*)(orow + tnf)      = r0;
        *(float4*)(orow + tnf + 64) = r1;
    }
}

// ---------------------------------------------------------------------------
// Fused per-(window, head) attention:
//   o = circular_conv_8x8(q*scale, k)  (per channel d)
//   attn = softmax(o @ v^T + bias[head])
//   y = attn @ v  -> scattered back to [B,192,H,W]
// grid: (2048 windows, 6 heads), 256 threads
// ---------------------------------------------------------------------------
__global__ __launch_bounds__(256) void attn_kernel()
{
    __shared__ float smem[8960];
    float* q_s    = smem;          // [64][34]
    float* k_s    = smem + 2176;   // [64][34]
    float* attn_s = smem;          // [64][68], overlays q/k after o-stage
    float* v_s    = smem + 4352;   // [64][36]
    float* o_s    = smem + 6656;   // [64][36]

    int win = blockIdx.x, head = blockIdx.y;
    int b = win >> 8, wi = win & 255;
    int h0 = (wi >> 4) * 8, w0 = (wi & 15) * 8;
    int tid = threadIdx.x;
    const float* qkv_b = g_qkv + (size_t)b * 576 * HW;
    const float SCALE = 0.17677669529663687f;   // 32^-0.5

    // ---- load q,k,v tiles ----
#pragma unroll
    for (int i = 0; i < 8; i++) {
        int idx = tid + i * 256;
        int d = idx >> 6, n = idx & 63;
        int pos = (h0 + (n >> 3)) * 128 + w0 + (n & 7);
        int cq = head * 32 + d;
        q_s[n * 34 + d] = qkv_b[(size_t)cq * HW + pos] * SCALE;
        k_s[n * 34 + d] = qkv_b[(size_t)(192 + cq) * HW + pos];
        v_s[n * 36 + d] = qkv_b[(size_t)(384 + cq) * HW + pos];
    }
    __syncthreads();

    // ---- o stage: 8x8 circular convolution per channel ----
    {
        int d = tid & 31, warp = tid >> 5;
        float acc[8] = {0, 0, 0, 0, 0, 0, 0, 0};
#pragma unroll
        for (int mi = 0; mi < 8; mi++) {
            int crow = (warp - mi) & 7;
            float krow[8];
#pragma unroll
            for (int j = 0; j < 8; j++) krow[j] = k_s[(crow * 8 + j) * 34 + d];
#pragma unroll
            for (int mj = 0; mj < 8; mj++) {
                float qv = q_s[(mi * 8 + mj) * 34 + d];
#pragma unroll
                for (int r = 0; r < 8; r++) acc[r] += qv * krow[(r - mj) & 7];
            }
        }
#pragma unroll
        for (int r = 0; r < 8; r++) o_s[(warp * 8 + r) * 36 + d] = acc[r];
    }
    __syncthreads();

    // ---- attn logits: 4x4 tile per thread ----
    {
        int tn4 = tid >> 4, tm4 = tid & 15;
        float acc[4][4];
#pragma unroll
        for (int i = 0; i < 4; i++) {
            float4 bb = *(const float4*)&g_bias[head * 4096 + (tn4 * 4 + i) * 64 + tm4 * 4];
            acc[i][0] = bb.x; acc[i][1] = bb.y; acc[i][2] = bb.z; acc[i][3] = bb.w;
        }
#pragma unroll
        for (int d4 = 0; d4 < 8; d4++) {
            float4 o4[4], v4[4];
#pragma unroll
            for (int i = 0; i < 4; i++) o4[i] = *(const float4*)&o_s[(tn4 * 4 + i) * 36 + d4 * 4];
#pragma unroll
            for (int j = 0; j < 4; j++) v4[j] = *(const float4*)&v_s[(tm4 * 4 + j) * 36 + d4 * 4];
#pragma unroll
            for (int i = 0; i < 4; i++)
#pragma unroll
                for (int j = 0; j < 4; j++)
                    acc[i][j] += o4[i].x * v4[j].x + o4[i].y * v4[j].y
                               + o4[i].z * v4[j].z + o4[i].w * v4[j].w;
        }
        // q/k region dead since last sync -> safe to overlay attn_s
#pragma unroll
        for (int i = 0; i < 4; i++) {
            float4 r = make_float4(acc[i][0], acc[i][1], acc[i][2], acc[i][3]);
            *(float4*)&attn_s[(tn4 * 4 + i) * 68 + tm4 * 4] = r;
        }
    }
    __syncthreads();

    // ---- softmax over m (4 threads per row + quad shuffles) ----
    {
        int n = tid >> 2;
        float* row = attn_s + n * 68 + (tid & 3) * 16;
        float mx = -1e30f;
#pragma unroll
        for (int m = 0; m < 16; m++) mx = fmaxf(mx, row[m]);
        mx = fmaxf(mx, __shfl_xor_sync(0xffffffffu, mx, 1));
        mx = fmaxf(mx, __shfl_xor_sync(0xffffffffu, mx, 2));
        float s = 0.0f;
#pragma unroll
        for (int m = 0; m < 16; m++) {
            float e = __expf(row[m] - mx);
            row[m] = e;
            s += e;
        }
        s += __shfl_xor_sync(0xffffffffu, s, 1);
        s += __shfl_xor_sync(0xffffffffu, s, 2);
        float inv = 1.0f / s;
#pragma unroll
        for (int m = 0; m < 16; m++) row[m] *= inv;
    }
    __syncthreads();

    // ---- y = attn @ v: 4n x 4d tile per thread (128 active), scatter to g_y ----
    if (tid < 128) {
        int tn4 = tid >> 3, td4 = tid & 7;
        float acc[4][4] = {};
#pragma unroll
        for (int m4 = 0; m4 < 16; m4++) {
            float4 a4[4];
#pragma unroll
            for (int i = 0; i < 4; i++) a4[i] = *(const float4*)&attn_s[(tn4 * 4 + i) * 68 + m4 * 4];
#pragma unroll
            for (int mm = 0; mm < 4; mm++) {
                float4 v4 = *(const float4*)&v_s[(m4 * 4 + mm) * 36 + td4 * 4];
#pragma unroll
                for (int i = 0; i < 4; i++) {
                    float am = (mm == 0) ? a4[i].x : (mm == 1) ? a4[i].y : (mm == 2) ? a4[i].z : a4[i].w;
                    acc[i][0] += am * v4.x; acc[i][1] += am * v4.y;
                    acc[i][2] += am * v4.z; acc[i][3] += am * v4.w;
                }
            }
        }
        float* yb = g_y + (size_t)b * 192 * HW;
#pragma unroll
        for (int i = 0; i < 4; i++) {
            int n = tn4 * 4 + i;
            int pos = (h0 + (n >> 3)) * 128 + w0 + (n & 7);
#pragma unroll
            for (int j = 0; j < 4; j++)
                yb[(size_t)(head * 32 + td4 * 4 + j) * HW + pos] = acc[i][j];
        }
    }
}

// ---------------------------------------------------------------------------
extern "C" void kernel_launch(void* const* d_in, const int* in_sizes, int n_in,
                              void* d_out, int out_size)
{
    const float* x      = (const float*)d_in[0];
    const float* V_w    = (const float*)d_in[1];
    const float* V_b    = (const float*)d_in[2];
    const float* QK_w   = (const float*)d_in[3];
    const float* QK_b   = (const float*)d_in[4];
    const float* proj_w = (const float*)d_in[5];
    const float* proj_b = (const float*)d_in[6];
    const float* mw1    = (const float*)d_in[7];
    const float* mb1    = (const float*)d_in[8];
    const float* mw2    = (const float*)d_in[9];
    const float* mb2    = (const float*)d_in[10];
    float* out = (float*)d_out;

    void* p;
    cudaGetSymbolAddress(&p, g_qkv); float* qkv = (float*)p;
    cudaGetSymbolAddress(&p, g_y);   float* y   = (float*)p;

    // 1) relative-position bias (meta MLP)
    bias_kernel<<<16, 256>>>(mw1, mb1, mw2, mb2);

    // 2) fused QK+V conv: rows [0,384)=QK, [384,576)=V  -> g_qkv
    gemm128<<<dim3(128, 5, 8), 256>>>(QK_w, QK_b, V_w, V_b, 384, 576,
                                      x, qkv, (size_t)576 * HW);

    // 3) fused windowed attention (circular conv + bias + softmax + AV)
    attn_kernel<<<dim3(2048, 6), 256>>>();

    // 4) output projection
    gemm128<<<dim3(128, 2, 8), 256>>>(proj_w, proj_b, proj_w, proj_b, 192, 192,
                                      y, out, (size_t)192 * HW);
}